// round 7
// baseline (speedup 1.0000x reference)
#include <cuda_runtime.h>
#include <math.h>

// DDSL spec: B=2, NV=NE=512, RES=(128,128) -> freq grid 128 x 65, J=2.
// ky-sweep phase-recurrence version:
//   block = (kx-pair, 13-ky chunk, batch); thread owns 2 ring-adjacent edges
//   (3 vertices). Stepping ky rotates each vertex phase by fixed 2*pi*y
//   (4 packed FMA) -> no sincos in the hot loop; only 4 MUFU rcp per step.
// All per-edge math packed over (kx, kx+1) via f32x2.

#define NVV    512
#define NEE    512
#define FXX    128
#define FY2    65
#define KXP    64          // kx-pairs
#define CHUNK  13
#define NCHUNK 5           // 5*13 = 65 ky values
#define BLOCK  256

#define NPART      (CHUNK * BLOCK)
#define SMEM_BYTES (2 * NPART * 8 + NEE * 4)   // sRbuf + sIbuf + scd = 55296

typedef unsigned long long u64;

__device__ __forceinline__ u64 pk2(float a, float b) {
    u64 r; asm("mov.b64 %0, {%1, %2};" : "=l"(r) : "f"(a), "f"(b)); return r;
}
__device__ __forceinline__ void upk(u64 v, float& a, float& b) {
    asm("mov.b64 {%0, %1}, %2;" : "=f"(a), "=f"(b) : "l"(v));
}
__device__ __forceinline__ u64 f2fma(u64 a, u64 b, u64 c) {
    u64 d; asm("fma.rn.f32x2 %0, %1, %2, %3;" : "=l"(d) : "l"(a), "l"(b), "l"(c)); return d;
}
__device__ __forceinline__ u64 f2add(u64 a, u64 b) {
    u64 d; asm("add.rn.f32x2 %0, %1, %2;" : "=l"(d) : "l"(a), "l"(b)); return d;
}
__device__ __forceinline__ u64 f2mul(u64 a, u64 b) {
    u64 d; asm("mul.rn.f32x2 %0, %1, %2;" : "=l"(d) : "l"(a), "l"(b)); return d;
}

__device__ __forceinline__ float fracr(float t) {
    // t - nearest_int(t), |t| < 2^22
    const float MAGIC = 12582912.0f;  // 1.5 * 2^23
    float g = __fadd_rn(t, MAGIC);
    float r = __fadd_rn(g, -MAGIC);
    return t - r;
}

// init vertex state at ky0: t (packed over kx pair), phase (c,s), rotation
// coeffs cw/sw = cos/sin(2*pi*y) splats, ys = y splat.
// NOTE: __sincosf writes SIN to the first pointer, COS to the second.
#define INITV(X, Y, T, C, S, CW, SW, YS)                                   \
    {                                                                      \
        float tl = fmaf((Y), fky0, (X) * fkx);                             \
        float th = tl + (X);                                               \
        float sl, cl, sh, chh;                                             \
        __sincosf(fracr(tl) * TWO_PI, &sl, &cl);                           \
        __sincosf(fracr(th) * TWO_PI, &sh, &chh);                          \
        T = pk2(tl, th); C = pk2(cl, chh); S = pk2(sl, sh);                \
        float cy, syv;                                                     \
        __sincosf(fracr(Y) * TWO_PI, &syv, &cy);   /* sin -> syv, cos -> cy */ \
        CW = pk2(cy, cy); SW = pk2(syv, syv); YS = pk2((Y), (Y));          \
    }

// edge contribution: numR = dt + ca*tb - cb*ta ; numI2 = sa*tb - sb*ta
// rc = cd / (ta*tb*dt) guarded; acc{R,I} {=, +=} num * rc
#define EVAL(TA, CA, SA, TB, CB, SB, CD, AR, AI, FIRST)                    \
    {                                                                      \
        u64 dt  = f2fma(TB, NEG1, TA);                                     \
        u64 den = f2mul(f2mul(TA, TB), dt);                                \
        u64 nta = f2mul(TA, NEG1);                                         \
        u64 nr  = f2fma(CB, nta, f2fma(CA, TB, dt));                       \
        u64 ni  = f2fma(SB, nta, f2mul(SA, TB));                           \
        float dlo, dhi; upk(den, dlo, dhi);                                \
        float rlo = (dlo != 0.0f) ? __fdividef(CD, dlo) : 0.0f;            \
        float rhi = (dhi != 0.0f) ? __fdividef(CD, dhi) : 0.0f;            \
        u64 rc = pk2(rlo, rhi);                                            \
        if (FIRST) { AR = f2mul(nr, rc); AI = f2mul(ni, rc); }             \
        else       { AR = f2fma(nr, rc, AR); AI = f2fma(ni, rc, AI); }     \
    }

// rotate phase by 2*pi*y and advance t by y
#define ROT(T, C, S, CW, SW, YS)                                           \
    {                                                                      \
        u64 ms = f2mul(S, SW);                                             \
        u64 nc = f2fma(ms, NEG1, f2mul(C, CW));                            \
        u64 ns = f2fma(C, SW, f2mul(S, CW));                               \
        C = nc; S = ns; T = f2add(T, YS);                                  \
    }

__global__ __launch_bounds__(BLOCK)
void ddsl_spec_kernel(const float* __restrict__ V,
                      const int*   __restrict__ E,
                      const float* __restrict__ D,
                      float*       __restrict__ out)
{
    extern __shared__ char smraw[];
    u64*   sRbuf = (u64*)smraw;             // [CHUNK*BLOCK]
    u64*   sIbuf = sRbuf + NPART;           // [CHUNK*BLOCK]
    float* scd   = (float*)(sIbuf + NPART); // [NEE]
    float* sx    = (float*)smraw;           // staging, overlaps sRbuf
    float* sy    = sx + NVV + 1;

    const int tid = threadIdx.x;
    const int kxp = blockIdx.x;
    const int ck  = blockIdx.y;
    const int b   = blockIdx.z;

    // ---- stage ring vertices + C*D ----
    for (int e = tid; e < NEE; e += BLOCK) {
        int i0 = E[(b * NEE + e) * 2 + 0];
        int i1 = E[(b * NEE + e) * 2 + 1];
        float ax = V[(b * NVV + i0) * 2 + 0];
        float ay = V[(b * NVV + i0) * 2 + 1];
        float bx = V[(b * NVV + i1) * 2 + 0];
        float by = V[(b * NVV + i1) * 2 + 1];
        sx[e] = ax; sy[e] = ay;
        scd[e] = (ax * by - ay * bx) * D[b * NEE + e];
        if (e == 0) { sx[NVV] = ax; sy[NVV] = ay; }   // ring wrap dup
    }
    __syncthreads();

    const int vv = 2 * tid;
    const float x0 = sx[vv],     y0 = sy[vv];
    const float x1 = sx[vv + 1], y1 = sy[vv + 1];
    const float x2 = sx[vv + 2], y2 = sy[vv + 2];
    const float cd0 = scd[vv], cd1 = scd[vv + 1];
    __syncthreads();   // staging consumed; sRbuf/sIbuf free to write

    const int fx0 = 2 * kxp;
    const int kx0 = (fx0 < FXX / 2) ? fx0 : fx0 - FXX;
    const float fkx  = (float)kx0;
    const int ky0 = ck * CHUNK;
    const float fky0 = (float)ky0;
    const float TWO_PI = 6.28318530717958647692f;
    const u64 NEG1 = pk2(-1.0f, -1.0f);

    u64 T0, C0, S0, CW0, SW0, YS0;
    u64 T1, C1, S1, CW1, SW1, YS1;
    u64 T2, C2, S2, CW2, SW2, YS2;
    INITV(x0, y0, T0, C0, S0, CW0, SW0, YS0);
    INITV(x1, y1, T1, C1, S1, CW1, SW1, YS1);
    INITV(x2, y2, T2, C2, S2, CW2, SW2, YS2);

#pragma unroll 1
    for (int st = 0; st < CHUNK; ++st) {
        u64 aR, aI;
        EVAL(T0, C0, S0, T1, C1, S1, cd0, aR, aI, 1);
        EVAL(T1, C1, S1, T2, C2, S2, cd1, aR, aI, 0);
        sRbuf[st * BLOCK + tid] = aR;
        sIbuf[st * BLOCK + tid] = aI;
        ROT(T0, C0, S0, CW0, SW0, YS0);
        ROT(T1, C1, S1, CW1, SW1, YS1);
        ROT(T2, C2, S2, CW2, SW2, YS2);
    }
    __syncthreads();

    // ---- final reduction: sum 256 lanes per (step, kx-slot) ----
    const int wid = tid >> 5, lane = tid & 31;
    const float SCALE = (float)(-16384.0 / (4.0 * 3.14159265358979323846
                                                * 3.14159265358979323846));
    for (int st = wid; st < CHUNK; st += 8) {
        u64 aR = sRbuf[st * BLOCK + lane];
        u64 aI = sIbuf[st * BLOCK + lane];
#pragma unroll
        for (int k = 1; k < 8; ++k) {
            aR = f2add(aR, sRbuf[st * BLOCK + lane + 32 * k]);
            aI = f2add(aI, sIbuf[st * BLOCK + lane + 32 * k]);
        }
#pragma unroll
        for (int off = 16; off > 0; off >>= 1) {
            aR = f2add(aR, __shfl_down_sync(0xFFFFFFFFu, aR, off));
            aI = f2add(aI, __shfl_down_sync(0xFFFFFFFFu, aI, off));
        }
        if (lane == 0) {
            float Rl, Rh, Il, Ih;
            upk(aR, Rl, Rh); upk(aI, Il, Ih);
            float oRl =  SCALE * Rl, oRh =  SCALE * Rh;
            float oIl = -SCALE * Il, oIh = -SCALE * Ih;   // aI held -Im
            int fy = ky0 + st;
            if (kxp == 0 && fy == 0) {
                // DC: F[:,0,0,:,:] = 8192*sum(C*D) in BOTH re and im
                float ssum = 0.0f;
                for (int e = 0; e < NEE; ++e) ssum += scd[e];
                oRl = 8192.0f * ssum;
                oIl = oRl;
            }
            int base = ((b * FXX + fx0) * FY2 + fy) * 2;
            out[base + 0] = oRl;
            out[base + 1] = oIl;
            out[base + 2 * FY2 + 0] = oRh;   // fx0 + 1
            out[base + 2 * FY2 + 1] = oIh;
        }
    }
}

extern "C" void kernel_launch(void* const* d_in, const int* in_sizes, int n_in,
                              void* d_out, int out_size)
{
    const float* V = (const float*)d_in[0];
    const int*   E = (const int*)  d_in[1];
    const float* D = (const float*)d_in[2];
    float* out = (float*)d_out;

    const int B = in_sizes[0] / (NVV * 2);   // 2
    cudaFuncSetAttribute(ddsl_spec_kernel,
                         cudaFuncAttributeMaxDynamicSharedMemorySize, SMEM_BYTES);
    dim3 grid(KXP, NCHUNK, B);               // (64, 5, 2) = 640 blocks
    ddsl_spec_kernel<<<grid, BLOCK, SMEM_BYTES>>>(V, E, D, out);
}